// round 6
// baseline (speedup 1.0000x reference)
#include <cuda_runtime.h>

// DeepSets: out[s,f] = sx_s*W[0,f] + sy_s*W[1,f] + cnt_s*b[f]
// Linearity: segment_sum(xW+b) == segment_sum(x)@W + cnt*b.
//
// SINGLE persistent kernel, exactly one resident wave (608 CTAs = 4/SM x 152):
//   Phase 1: 4864 warps each stream a contiguous float4 range of x
//            (ids sorted -> per-warp boundary discovery; <=2 segs typical),
//            accumulate (sx, sy, cnt) per segment via atomics.
//   Software grid barrier (generation counter, wrap-safe, never reset ->
//            deterministic across graph replays; all CTAs co-resident).
//   Phase 2: same threads expand to [4096,64] with float4 stores while the
//            accumulators are L2-hot, then reset them (zero-at-entry invariant;
//            device globals start zeroed).

#define FEAT_OUT 64
#define NSEG_MAX 4096
#define K2_CTAS 608
#define K2_THREADS 256
#define K2_WARPS (K2_CTAS * (K2_THREADS / 32))

__device__ float    g_px[NSEG_MAX];
__device__ float    g_py[NSEG_MAX];
__device__ int      g_cnt[NSEG_MAX];
__device__ unsigned g_arrive;   // generation barrier counter (monotonic)

__device__ __forceinline__ float warp_sum(float v)
{
    #pragma unroll
    for (int o = 16; o > 0; o >>= 1) v += __shfl_xor_sync(0xFFFFFFFFu, v, o);
    return v;
}

// Warp-collective lower_bound of `target` in ids[lo,hi) (sorted); all lanes
// return the same value. ~2 rounds for ranges < 1089.
__device__ __forceinline__ int warp_lower_bound(const int* __restrict__ ids,
                                                int lo, int hi, int target)
{
    const int lane = threadIdx.x & 31;
    while (hi > lo) {
        const int m = hi - lo;
        const int p = lo + (int)(((long long)m * (lane + 1)) / 33);
        const int v = __ldg(&ids[p]);
        const unsigned pred = __ballot_sync(0xFFFFFFFFu, v < target);
        const int c = __popc(pred);
        int nlo, nhi;
        if (c == 0)  nlo = lo; else nlo = lo + (int)(((long long)m * c) / 33) + 1;
        if (c == 32) nhi = hi; else nhi = lo + (int)(((long long)m * (c + 1)) / 33);
        lo = nlo; hi = nhi;
    }
    return lo;
}

__global__ __launch_bounds__(K2_THREADS)
void deepsets_fused_kernel(const float4* __restrict__ xb,   // [N/2] point pairs
                           const float2* __restrict__ x2,   // [N]
                           const int*    __restrict__ ids,  // [N] sorted
                           const float*  __restrict__ W,    // [2,64]
                           const float*  __restrict__ b,    // [64]
                           float*        __restrict__ out,  // [nseg,64]
                           int N, int NF4, int num_segments)
{
    const int lane = threadIdx.x & 31;
    const int gw   = blockIdx.x * (K2_THREADS / 32) + (threadIdx.x >> 5);

    // ---------------- Phase 1: streaming segment sums --------------------
    if ((N & 1) && gw == 0 && lane == 0) {
        const int s = __ldg(&ids[N - 1]);
        const float2 p = __ldg(&x2[N - 1]);
        atomicAdd(&g_px[s], p.x);
        atomicAdd(&g_py[s], p.y);
        atomicAdd(&g_cnt[s], 1);
    }

    const int Q  = (NF4 + K2_WARPS - 1) / K2_WARPS;
    const int f0 = gw * Q;
    const int f1 = min(f0 + Q, NF4);

    if (f0 < f1) {
        const int p0   = 2 * f0;
        const int pend = 2 * f1;
        const int s_lo = __ldg(&ids[p0]);
        const int s_hi = __ldg(&ids[pend - 1]);
        const int nseg = s_hi - s_lo + 1;

        if (nseg == 1) {
            float tx = 0.f, ty = 0.f;
            for (int j = f0 + lane; j < f1; j += 128) {
                const int j1 = j + 32, j2 = j + 64, j3 = j + 96;
                float4 v0 = __ldg(&xb[j]);
                float4 v1 = make_float4(0.f,0.f,0.f,0.f);
                float4 v2 = make_float4(0.f,0.f,0.f,0.f);
                float4 v3 = make_float4(0.f,0.f,0.f,0.f);
                if (j1 < f1) v1 = __ldg(&xb[j1]);
                if (j2 < f1) v2 = __ldg(&xb[j2]);
                if (j3 < f1) v3 = __ldg(&xb[j3]);
                tx += (v0.x+v0.z) + (v1.x+v1.z) + (v2.x+v2.z) + (v3.x+v3.z);
                ty += (v0.y+v0.w) + (v1.y+v1.w) + (v2.y+v2.w) + (v3.y+v3.w);
            }
            tx = warp_sum(tx); ty = warp_sum(ty);
            if (lane == 0) {
                atomicAdd(&g_px[s_lo], tx);
                atomicAdd(&g_py[s_lo], ty);
                atomicAdd(&g_cnt[s_lo], pend - p0);
            }
        } else if (nseg == 2) {
            const int B1 = warp_lower_bound(ids, p0 + 1, pend, s_lo + 1);
            const int jA = (B1 + 1) >> 1;
            const int jB =  B1      >> 1;
            float tx = 0.f, ty = 0.f, s1x = 0.f, s1y = 0.f;
            for (int j = f0 + lane; j < f1; j += 128) {
                const int j1 = j + 32, j2 = j + 64, j3 = j + 96;
                float4 v0 = __ldg(&xb[j]);
                float4 v1 = make_float4(0.f,0.f,0.f,0.f);
                float4 v2 = make_float4(0.f,0.f,0.f,0.f);
                float4 v3 = make_float4(0.f,0.f,0.f,0.f);
                if (j1 < f1) v1 = __ldg(&xb[j1]);
                if (j2 < f1) v2 = __ldg(&xb[j2]);
                if (j3 < f1) v3 = __ldg(&xb[j3]);
                tx += (v0.x+v0.z) + (v1.x+v1.z) + (v2.x+v2.z) + (v3.x+v3.z);
                ty += (v0.y+v0.w) + (v1.y+v1.w) + (v2.y+v2.w) + (v3.y+v3.w);
                s1x += (j  >= jA ? v0.x : 0.f) + (j  >= jB ? v0.z : 0.f)
                     + (j1 >= jA ? v1.x : 0.f) + (j1 >= jB ? v1.z : 0.f)
                     + (j2 >= jA ? v2.x : 0.f) + (j2 >= jB ? v2.z : 0.f)
                     + (j3 >= jA ? v3.x : 0.f) + (j3 >= jB ? v3.z : 0.f);
                s1y += (j  >= jA ? v0.y : 0.f) + (j  >= jB ? v0.w : 0.f)
                     + (j1 >= jA ? v1.y : 0.f) + (j1 >= jB ? v1.w : 0.f)
                     + (j2 >= jA ? v2.y : 0.f) + (j2 >= jB ? v2.w : 0.f)
                     + (j3 >= jA ? v3.y : 0.f) + (j3 >= jB ? v3.w : 0.f);
            }
            tx  = warp_sum(tx);  ty  = warp_sum(ty);
            s1x = warp_sum(s1x); s1y = warp_sum(s1y);
            if (lane == 0) {
                atomicAdd(&g_px[s_lo],      tx - s1x);
                atomicAdd(&g_py[s_lo],      ty - s1y);
                atomicAdd(&g_cnt[s_lo],     B1 - p0);
                atomicAdd(&g_px[s_lo + 1],  s1x);
                atomicAdd(&g_py[s_lo + 1],  s1y);
                atomicAdd(&g_cnt[s_lo + 1], pend - B1);
            }
        } else {
            // Rare generic path: walk segments, local searches.
            int lo = p0;
            for (int s = s_lo; s <= s_hi; s++) {
                const int hi_s = (s == s_hi) ? pend
                                             : warp_lower_bound(ids, lo, pend, s + 1);
                if (hi_s > lo) {
                    float sx = 0.f, sy = 0.f;
                    for (int i = lo + lane; i < hi_s; i += 32) {
                        float2 p = __ldg(&x2[i]);
                        sx += p.x; sy += p.y;
                    }
                    sx = warp_sum(sx); sy = warp_sum(sy);
                    if (lane == 0) {
                        atomicAdd(&g_px[s], sx);
                        atomicAdd(&g_py[s], sy);
                        atomicAdd(&g_cnt[s], hi_s - lo);
                    }
                    lo = hi_s;
                }
            }
        }
    }

    // ---------------- Grid barrier (generation counter) ------------------
    __syncthreads();                 // CTA's atomics all issued
    if (threadIdx.x == 0) {
        __threadfence();             // publish this CTA's accumulations
        const unsigned ticket = atomicAdd(&g_arrive, 1u);
        const unsigned target = (ticket / K2_CTAS + 1u) * K2_CTAS;
        while ((int)(*(volatile unsigned*)&g_arrive - target) < 0)
            __nanosleep(64);
        __threadfence();             // acquire others' accumulations
    }
    __syncthreads();

    // ---------------- Phase 2: epilogue (float4 per thread) --------------
    const int gid = blockIdx.x * K2_THREADS + threadIdx.x;
    const int n_out4 = num_segments * (FEAT_OUT / 4);   // 65536
    if (gid < n_out4) {
        const int s  = gid >> 4;           // 16 float4 per segment
        const int fq = (gid & 15) << 2;    // feature quad base
        const float sx  = g_px[s];
        const float sy  = g_py[s];
        const float cnt = (float)g_cnt[s];
        const float4 w0 = __ldg((const float4*)&W[fq]);
        const float4 w1 = __ldg((const float4*)&W[FEAT_OUT + fq]);
        const float4 bb = __ldg((const float4*)&b[fq]);
        float4 o;
        o.x = fmaf(sx, w0.x, fmaf(sy, w1.x, cnt * bb.x));
        o.y = fmaf(sx, w0.y, fmaf(sy, w1.y, cnt * bb.y));
        o.z = fmaf(sx, w0.z, fmaf(sy, w1.z, cnt * bb.z));
        o.w = fmaf(sx, w0.w, fmaf(sy, w1.w, cnt * bb.w));
        reinterpret_cast<float4*>(out)[gid] = o;
    }
    __syncthreads();   // all reads of this block's 16 segments complete

    // Reset: block b owns segments [16b, 16b+16) entirely (reads above are
    // intra-block), so resetting here is race-free and restores zeros.
    if (blockIdx.x < (unsigned)(num_segments / 16) && threadIdx.x < 16) {
        const int s = blockIdx.x * 16 + threadIdx.x;
        g_px[s]  = 0.f;
        g_py[s]  = 0.f;
        g_cnt[s] = 0;
    }
}

extern "C" void kernel_launch(void* const* d_in, const int* in_sizes, int n_in,
                              void* d_out, int out_size)
{
    const float* xf  = (const float*)d_in[0];    // [N,2]
    const int*   ids = (const int*)d_in[1];      // [N] sorted
    const float* W   = (const float*)d_in[2];    // [2,64]
    const float* b   = (const float*)d_in[3];    // [64]
    float* out = (float*)d_out;

    const int N   = in_sizes[0] / 2;
    const int NF4 = N / 2;
    const int num_segments = out_size / FEAT_OUT;   // 4096

    deepsets_fused_kernel<<<K2_CTAS, K2_THREADS>>>(
        (const float4*)xf, (const float2*)xf, ids, W, b, out,
        N, NF4, num_segments);
}

// round 8
// speedup vs baseline: 1.0175x; 1.0175x over previous
#include <cuda_runtime.h>

// DeepSets: out[s,f] = sx_s*W[0,f] + sy_s*W[1,f] + cnt_s*b[f]
// Linearity: segment_sum(xW+b) == segment_sum(x)@W + cnt*b.
//
// ONE persistent kernel, one resident wave (608 CTAs x 384 thr = 48 warps/SM):
//  Phase 1a: every warp streams its contiguous float4 range UNCONDITIONALLY
//            for (tx, ty) totals — x loads start immediately (no ids dep).
//  Phase 1b: per boundary in the warp's range (almost always 0 or 1):
//            warp-wide lower_bound + SUFFIX pass over the L2-hot tail;
//            per-segment sums = adjacent suffix differences.
//  Grid barrier (generation counter, wrap-safe, never reset).
//  Phase 2:  epilogue expands to [4096,64] with float4 stores; accumulators
//            are reset BY THE SAME THREADS THAT READ THEM (race-free for any
//            block size with 16 threads/segment), restoring zero-at-entry.

#define FEAT_OUT 64
#define NSEG_MAX 4096
#define K2_CTAS 608
#define K2_THREADS 384
#define K2_WARPS (K2_CTAS * (K2_THREADS / 32))

__device__ float    g_px[NSEG_MAX];
__device__ float    g_py[NSEG_MAX];
__device__ int      g_cnt[NSEG_MAX];
__device__ unsigned g_arrive;   // monotonic generation barrier counter

__device__ __forceinline__ float warp_sum(float v)
{
    #pragma unroll
    for (int o = 16; o > 0; o >>= 1) v += __shfl_xor_sync(0xFFFFFFFFu, v, o);
    return v;
}

// Warp-collective lower_bound of `target` in ids[lo,hi); all lanes return the
// same value. 2 rounds for ranges < 1089.
__device__ __forceinline__ int warp_lower_bound(const int* __restrict__ ids,
                                                int lo, int hi, int target)
{
    const int lane = threadIdx.x & 31;
    while (hi > lo) {
        const int m = hi - lo;
        const int p = lo + (int)(((long long)m * (lane + 1)) / 33);
        const int v = __ldg(&ids[p]);
        const unsigned pred = __ballot_sync(0xFFFFFFFFu, v < target);
        const int c = __popc(pred);
        int nlo, nhi;
        if (c == 0)  nlo = lo; else nlo = lo + (int)(((long long)m * c) / 33) + 1;
        if (c == 32) nhi = hi; else nhi = lo + (int)(((long long)m * (c + 1)) / 33);
        lo = nlo; hi = nhi;
    }
    return lo;
}

__global__ __launch_bounds__(K2_THREADS)
void deepsets_fused_kernel(const float4* __restrict__ xb,   // [N/2] point pairs
                           const float2* __restrict__ x2,   // [N]
                           const int*    __restrict__ ids,  // [N] sorted
                           const float*  __restrict__ W,    // [2,64]
                           const float*  __restrict__ b,    // [64]
                           float*        __restrict__ out,  // [nseg,64]
                           int N, int NF4, int num_segments)
{
    const int lane = threadIdx.x & 31;
    const int gw   = blockIdx.x * (K2_THREADS / 32) + (threadIdx.x >> 5);

    if ((N & 1) && gw == 0 && lane == 0) {
        const int s = __ldg(&ids[N - 1]);
        const float2 p = __ldg(&x2[N - 1]);
        atomicAdd(&g_px[s], p.x);
        atomicAdd(&g_py[s], p.y);
        atomicAdd(&g_cnt[s], 1);
    }

    const int Q  = (NF4 + K2_WARPS - 1) / K2_WARPS;
    const int f0 = gw * Q;
    const int f1 = min(f0 + Q, NF4);

    if (f0 < f1) {
        const int p0   = 2 * f0;
        const int pend = 2 * f1;
        // Endpoint id loads issue here; consumed after the totals loop, so
        // their latency overlaps the stream.
        const int s_lo = __ldg(&ids[p0]);
        const int s_hi = __ldg(&ids[pend - 1]);

        // -------- Phase 1a: unconditional totals stream (MLP=4) ----------
        float tx = 0.f, ty = 0.f;
        for (int j = f0 + lane; j < f1; j += 128) {
            const int j1 = j + 32, j2 = j + 64, j3 = j + 96;
            float4 v0 = __ldg(&xb[j]);
            float4 v1 = make_float4(0.f,0.f,0.f,0.f);
            float4 v2 = make_float4(0.f,0.f,0.f,0.f);
            float4 v3 = make_float4(0.f,0.f,0.f,0.f);
            if (j1 < f1) v1 = __ldg(&xb[j1]);
            if (j2 < f1) v2 = __ldg(&xb[j2]);
            if (j3 < f1) v3 = __ldg(&xb[j3]);
            tx += (v0.x+v0.z) + (v1.x+v1.z) + (v2.x+v2.z) + (v3.x+v3.z);
            ty += (v0.y+v0.w) + (v1.y+v1.w) + (v2.y+v2.w) + (v3.y+v3.w);
        }
        tx = warp_sum(tx); ty = warp_sum(ty);

        // -------- Phase 1b: boundary suffixes (x range is L2-hot) --------
        const int nseg = s_hi - s_lo + 1;
        float prevSx = tx, prevSy = ty;   // suffix from p0 == total
        int   prevB  = p0;
        int   searchLo = p0 + 1;

        for (int m = 1; m < nseg; m++) {
            const int Bm = warp_lower_bound(ids, searchLo, pend, s_lo + m);
            searchLo = Bm;
            const int jA = (Bm + 1) >> 1;   // even point 2j included iff j>=jA
            const int jB =  Bm      >> 1;   // odd point 2j+1 included iff j>=jB
            float sx = 0.f, sy = 0.f;
            for (int j = jB + lane; j < f1; j += 128) {
                const int j1 = j + 32, j2 = j + 64, j3 = j + 96;
                float4 v0 = __ldg(&xb[j]);
                float4 v1 = make_float4(0.f,0.f,0.f,0.f);
                float4 v2 = make_float4(0.f,0.f,0.f,0.f);
                float4 v3 = make_float4(0.f,0.f,0.f,0.f);
                if (j1 < f1) v1 = __ldg(&xb[j1]);
                if (j2 < f1) v2 = __ldg(&xb[j2]);
                if (j3 < f1) v3 = __ldg(&xb[j3]);
                sx += (j  >= jA ? v0.x : 0.f) + v0.z
                    + (j1 >= jA ? v1.x : 0.f) + v1.z
                    + (j2 >= jA ? v2.x : 0.f) + v2.z
                    + (j3 >= jA ? v3.x : 0.f) + v3.z;
                sy += (j  >= jA ? v0.y : 0.f) + v0.w
                    + (j1 >= jA ? v1.y : 0.f) + v1.w
                    + (j2 >= jA ? v2.y : 0.f) + v2.w
                    + (j3 >= jA ? v3.y : 0.f) + v3.w;
            }
            sx = warp_sum(sx); sy = warp_sum(sy);
            if (lane == 0) {
                atomicAdd(&g_px[s_lo + m - 1],  prevSx - sx);
                atomicAdd(&g_py[s_lo + m - 1],  prevSy - sy);
                atomicAdd(&g_cnt[s_lo + m - 1], Bm - prevB);
            }
            prevSx = sx; prevSy = sy; prevB = Bm;
        }
        if (lane == 0) {
            atomicAdd(&g_px[s_hi],  prevSx);
            atomicAdd(&g_py[s_hi],  prevSy);
            atomicAdd(&g_cnt[s_hi], pend - prevB);
        }
    }

    // ---------------- Grid barrier (generation counter) ------------------
    __syncthreads();
    if (threadIdx.x == 0) {
        __threadfence();
        const unsigned ticket = atomicAdd(&g_arrive, 1u);
        const unsigned target = (ticket / K2_CTAS + 1u) * K2_CTAS;
        while ((int)(*(volatile unsigned*)&g_arrive - target) < 0)
            __nanosleep(64);
        __threadfence();
    }
    __syncthreads();

    // ---------------- Phase 2: epilogue (float4 per thread) --------------
    const int gid = blockIdx.x * K2_THREADS + threadIdx.x;
    const int n_out4 = num_segments * (FEAT_OUT / 4);   // 65536
    if (gid < n_out4) {
        const int s  = gid >> 4;           // 16 threads (one float4 each) / seg
        const int fq = (gid & 15) << 2;    // feature quad base
        const float sx  = g_px[s];
        const float sy  = g_py[s];
        const float cnt = (float)g_cnt[s];
        const float4 w0 = __ldg((const float4*)&W[fq]);
        const float4 w1 = __ldg((const float4*)&W[FEAT_OUT + fq]);
        const float4 bb = __ldg((const float4*)&b[fq]);
        float4 o;
        o.x = fmaf(sx, w0.x, fmaf(sy, w1.x, cnt * bb.x));
        o.y = fmaf(sx, w0.y, fmaf(sy, w1.y, cnt * bb.y));
        o.z = fmaf(sx, w0.z, fmaf(sy, w1.z, cnt * bb.z));
        o.w = fmaf(sx, w0.w, fmaf(sy, w1.w, cnt * bb.w));
        reinterpret_cast<float4*>(out)[gid] = o;
    }
    __syncthreads();   // this block's reads of its segments are complete

    // Reset by the SAME threads that read each segment (16 threads/segment,
    // all within this block since K2_THREADS % 16 == 0). Race-free.
    if (gid < n_out4) {
        const int s = gid >> 4;
        const int r = gid & 15;
        if      (r == 0) g_px[s]  = 0.f;
        else if (r == 1) g_py[s]  = 0.f;
        else if (r == 2) g_cnt[s] = 0;
    }
}

extern "C" void kernel_launch(void* const* d_in, const int* in_sizes, int n_in,
                              void* d_out, int out_size)
{
    const float* xf  = (const float*)d_in[0];    // [N,2]
    const int*   ids = (const int*)d_in[1];      // [N] sorted
    const float* W   = (const float*)d_in[2];    // [2,64]
    const float* b   = (const float*)d_in[3];    // [64]
    float* out = (float*)d_out;

    const int N   = in_sizes[0] / 2;
    const int NF4 = N / 2;
    const int num_segments = out_size / FEAT_OUT;   // 4096

    deepsets_fused_kernel<<<K2_CTAS, K2_THREADS>>>(
        (const float4*)xf, (const float2*)xf, ids, W, b, out,
        N, NF4, num_segments);
}